// round 7
// baseline (speedup 1.0000x reference)
#include <cuda_runtime.h>
#include <math_constants.h>

#define BATCH 131072
#define NUM_CLASSES 1000
#define C4 250                 // float4 chunks per row (1000 floats)
#define MAIN_BLOCK 256
#define WARPS_PER_BLOCK (MAIN_BLOCK / 32)
#define GRID_BLOCKS (BATCH / WARPS_PER_BLOCK)   // 16384, exact

// Zero-initialized at module load; re-zeroed by the last block of every run,
// so each graph replay starts clean. No separate zero/finalize kernels.
__device__ int g_counts[NUM_CLASSES];
__device__ int g_hits[NUM_CLASSES];
__device__ unsigned int g_done;

__global__ void __launch_bounds__(MAIN_BLOCK)
mean_recall_fused_kernel(const float4* __restrict__ y_pred,
                         const float4* __restrict__ y_true,
                         float* __restrict__ out) {
    // ---------------- Phase 1: per-warp dual argmax + histogram ----------------
    const int warp_id = (blockIdx.x * WARPS_PER_BLOCK) + (threadIdx.x >> 5);
    const int lane    = threadIdx.x & 31;

    const float4* __restrict__ rp = y_pred + (size_t)warp_id * C4;
    const float4* __restrict__ rt = y_true + (size_t)warp_id * C4;

    // Unpredicated loads: clamp index to 249. Duplicated chunk-249 reads are
    // harmless for argmax (strict '>' keeps the first occurrence; ties resolve
    // by smaller index in the warp reduce). 16 independent LDG.128 per lane.
    float4 a[8], b[8];
    int idx[8];
    #pragma unroll
    for (int k = 0; k < 8; k++) {
        const int i = min(k * 32 + lane, C4 - 1);
        idx[k] = i * 4;
        a[k] = __ldg(rp + i);
        b[k] = __ldg(rt + i);
    }

    float pbest = -CUDART_INF_F; int pidx = 0;
    float tbest = -CUDART_INF_F; int tidx = 0;
    #pragma unroll
    for (int k = 0; k < 8; k++) {
        const int base = idx[k];
        if (a[k].x > pbest) { pbest = a[k].x; pidx = base + 0; }
        if (a[k].y > pbest) { pbest = a[k].y; pidx = base + 1; }
        if (a[k].z > pbest) { pbest = a[k].z; pidx = base + 2; }
        if (a[k].w > pbest) { pbest = a[k].w; pidx = base + 3; }
        if (b[k].x > tbest) { tbest = b[k].x; tidx = base + 0; }
        if (b[k].y > tbest) { tbest = b[k].y; tidx = base + 1; }
        if (b[k].z > tbest) { tbest = b[k].z; tidx = base + 2; }
        if (b[k].w > tbest) { tbest = b[k].w; tidx = base + 3; }
    }

    // Warp argmax reduce; tie-break toward smaller index (first occurrence).
    #pragma unroll
    for (int off = 16; off > 0; off >>= 1) {
        float pv = __shfl_down_sync(0xFFFFFFFFu, pbest, off);
        int   pi = __shfl_down_sync(0xFFFFFFFFu, pidx,  off);
        if (pv > pbest || (pv == pbest && pi < pidx)) { pbest = pv; pidx = pi; }
        float tv = __shfl_down_sync(0xFFFFFFFFu, tbest, off);
        int   ti = __shfl_down_sync(0xFFFFFFFFu, tidx,  off);
        if (tv > tbest || (tv == tbest && ti < tidx)) { tbest = tv; tidx = ti; }
    }

    if (lane == 0) {
        atomicAdd(&g_counts[tidx], 1);
        if (pidx == tidx) atomicAdd(&g_hits[tidx], 1);
    }

    // ---------------- Phase 2: last block finalizes + resets ----------------
    __shared__ bool s_is_last;
    __syncthreads();                 // all warps' atomics issued
    if (threadIdx.x == 0) {
        __threadfence();             // release: this block's atomics visible
        unsigned int t = atomicAdd(&g_done, 1u);
        s_is_last = (t == (unsigned int)(GRID_BLOCKS - 1));
    }
    __syncthreads();
    if (!s_is_last) return;
    __threadfence();                 // acquire: all blocks' hist writes visible

    const int tid = threadIdx.x;
    float rec_sum = 0.0f, n_present = 0.0f;
    for (int c = tid; c < NUM_CLASSES; c += MAIN_BLOCK) {
        const int cnt = __ldcg(&g_counts[c]);
        if (cnt > 0) {
            n_present += 1.0f;
            rec_sum   += (float)__ldcg(&g_hits[c]) / (float)cnt;
        }
    }

    __shared__ float s_rec[WARPS_PER_BLOCK];
    __shared__ float s_prs[WARPS_PER_BLOCK];
    #pragma unroll
    for (int off = 16; off > 0; off >>= 1) {
        rec_sum   += __shfl_down_sync(0xFFFFFFFFu, rec_sum,   off);
        n_present += __shfl_down_sync(0xFFFFFFFFu, n_present, off);
    }
    const int warp = tid >> 5;
    if (lane == 0) { s_rec[warp] = rec_sum; s_prs[warp] = n_present; }
    __syncthreads();
    if (warp == 0) {
        rec_sum   = (lane < WARPS_PER_BLOCK) ? s_rec[lane] : 0.0f;
        n_present = (lane < WARPS_PER_BLOCK) ? s_prs[lane] : 0.0f;
        #pragma unroll
        for (int off = 4; off > 0; off >>= 1) {
            rec_sum   += __shfl_down_sync(0xFFFFFFFFu, rec_sum,   off);
            n_present += __shfl_down_sync(0xFFFFFFFFu, n_present, off);
        }
        if (lane == 0)
            out[0] = (n_present > 0.0f) ? -(rec_sum / n_present) : 0.0f;
    }

    // Reset state for the next graph replay. The __syncthreads() orders all
    // histogram reads above before these writes.
    __syncthreads();
    for (int c = tid; c < NUM_CLASSES; c += MAIN_BLOCK) {
        g_counts[c] = 0;
        g_hits[c]   = 0;
    }
    if (tid == 0) {
        __threadfence();
        g_done = 0u;
    }
}

extern "C" void kernel_launch(void* const* d_in, const int* in_sizes, int n_in,
                              void* d_out, int out_size) {
    const float4* y_pred = (const float4*)d_in[0];
    const float4* y_true = (const float4*)d_in[1];
    float* out = (float*)d_out;

    mean_recall_fused_kernel<<<GRID_BLOCKS, MAIN_BLOCK>>>(y_pred, y_true, out);
}

// round 8
// speedup vs baseline: 1.0238x; 1.0238x over previous
#include <cuda_runtime.h>
#include <math_constants.h>

#define BATCH 131072
#define NUM_CLASSES 1000
#define C4 250                 // float4 chunks per row (1000 floats)
#define MAIN_BLOCK 256
#define WARPS_PER_BLOCK (MAIN_BLOCK / 32)
#define GRID_BLOCKS (BATCH / WARPS_PER_BLOCK)   // 16384, exact

// Zero-initialized at module load. The finalize kernel re-zeros after use, so
// every graph replay starts from the same (zeroed) state. No zero kernel.
__device__ int g_counts[NUM_CLASSES];
__device__ int g_hits[NUM_CLASSES];

// ---------------------------------------------------------------------------
// Kernel 1: one warp per row. Dual argmax (pred & true), first-index
// tie-break, histogram atomics. Pure streaming — no epilogue fences.
// ---------------------------------------------------------------------------
__global__ void __launch_bounds__(MAIN_BLOCK)
argmax_hist_kernel(const float4* __restrict__ y_pred,
                   const float4* __restrict__ y_true) {
    const int warp_id = (blockIdx.x * WARPS_PER_BLOCK) + (threadIdx.x >> 5);
    const int lane    = threadIdx.x & 31;

    const float4* __restrict__ rp = y_pred + (size_t)warp_id * C4;
    const float4* __restrict__ rt = y_true + (size_t)warp_id * C4;

    // Unpredicated loads: clamp index to 249. Duplicated chunk-249 reads are
    // harmless for argmax (strict '>' keeps the first occurrence; cross-lane
    // ties resolve by smaller index in the warp reduce). 16 independent
    // LDG.128 per lane; __ldcs = evict-first (data touched exactly once).
    float4 a[8], b[8];
    int idx[8];
    #pragma unroll
    for (int k = 0; k < 8; k++) {
        const int i = min(k * 32 + lane, C4 - 1);
        idx[k] = i * 4;
        a[k] = __ldcs(rp + i);
        b[k] = __ldcs(rt + i);
    }

    float pbest = -CUDART_INF_F; int pidx = 0;
    float tbest = -CUDART_INF_F; int tidx = 0;
    #pragma unroll
    for (int k = 0; k < 8; k++) {
        const int base = idx[k];
        if (a[k].x > pbest) { pbest = a[k].x; pidx = base + 0; }
        if (a[k].y > pbest) { pbest = a[k].y; pidx = base + 1; }
        if (a[k].z > pbest) { pbest = a[k].z; pidx = base + 2; }
        if (a[k].w > pbest) { pbest = a[k].w; pidx = base + 3; }
        if (b[k].x > tbest) { tbest = b[k].x; tidx = base + 0; }
        if (b[k].y > tbest) { tbest = b[k].y; tidx = base + 1; }
        if (b[k].z > tbest) { tbest = b[k].z; tidx = base + 2; }
        if (b[k].w > tbest) { tbest = b[k].w; tidx = base + 3; }
    }

    // Warp argmax reduce; tie-break toward smaller index (first occurrence).
    #pragma unroll
    for (int off = 16; off > 0; off >>= 1) {
        float pv = __shfl_down_sync(0xFFFFFFFFu, pbest, off);
        int   pi = __shfl_down_sync(0xFFFFFFFFu, pidx,  off);
        if (pv > pbest || (pv == pbest && pi < pidx)) { pbest = pv; pidx = pi; }
        float tv = __shfl_down_sync(0xFFFFFFFFu, tbest, off);
        int   ti = __shfl_down_sync(0xFFFFFFFFu, tidx,  off);
        if (tv > tbest || (tv == tbest && ti < tidx)) { tbest = tv; tidx = ti; }
    }

    if (lane == 0) {
        atomicAdd(&g_counts[tidx], 1);
        if (pidx == tidx) atomicAdd(&g_hits[tidx], 1);
    }
}

// ---------------------------------------------------------------------------
// Kernel 2: reduce 1000 classes -> -mean_recall, then reset histograms for
// the next graph replay.
// ---------------------------------------------------------------------------
__global__ void __launch_bounds__(256)
finalize_kernel(float* __restrict__ out) {
    const int tid = threadIdx.x;
    float rec_sum = 0.0f, n_present = 0.0f;

    #pragma unroll
    for (int c = tid; c < NUM_CLASSES; c += 256) {
        const int cnt = g_counts[c];
        if (cnt > 0) {
            n_present += 1.0f;
            rec_sum   += (float)g_hits[c] / (float)cnt;
        }
    }

    __shared__ float s_rec[8];
    __shared__ float s_prs[8];
    #pragma unroll
    for (int off = 16; off > 0; off >>= 1) {
        rec_sum   += __shfl_down_sync(0xFFFFFFFFu, rec_sum,   off);
        n_present += __shfl_down_sync(0xFFFFFFFFu, n_present, off);
    }
    const int warp = tid >> 5;
    const int lane = tid & 31;
    if (lane == 0) { s_rec[warp] = rec_sum; s_prs[warp] = n_present; }
    __syncthreads();
    if (warp == 0) {
        rec_sum   = (lane < 8) ? s_rec[lane] : 0.0f;
        n_present = (lane < 8) ? s_prs[lane] : 0.0f;
        #pragma unroll
        for (int off = 4; off > 0; off >>= 1) {
            rec_sum   += __shfl_down_sync(0xFFFFFFFFu, rec_sum,   off);
            n_present += __shfl_down_sync(0xFFFFFFFFu, n_present, off);
        }
        if (lane == 0)
            out[0] = (n_present > 0.0f) ? -(rec_sum / n_present) : 0.0f;
    }

    // Reset for the next replay. __syncthreads orders all reads above
    // before the writes below.
    __syncthreads();
    #pragma unroll
    for (int c = tid; c < NUM_CLASSES; c += 256) {
        g_counts[c] = 0;
        g_hits[c]   = 0;
    }
}

// ---------------------------------------------------------------------------
extern "C" void kernel_launch(void* const* d_in, const int* in_sizes, int n_in,
                              void* d_out, int out_size) {
    const float4* y_pred = (const float4*)d_in[0];
    const float4* y_true = (const float4*)d_in[1];
    float* out = (float*)d_out;

    argmax_hist_kernel<<<GRID_BLOCKS, MAIN_BLOCK>>>(y_pred, y_true);
    finalize_kernel<<<1, 256>>>(out);
}

// round 9
// speedup vs baseline: 1.0264x; 1.0025x over previous
#include <cuda_runtime.h>
#include <math_constants.h>

#define BATCH 131072
#define NUM_CLASSES 1000
#define C4 250                 // float4 chunks per row (1000 floats)
#define MAIN_BLOCK 256
#define WARPS_PER_BLOCK (MAIN_BLOCK / 32)
#define GRID_BLOCKS (BATCH / WARPS_PER_BLOCK)   // 16384, exact

// Zero-initialized at module load. The finalize kernel re-zeros after use, so
// every graph replay starts from the same (zeroed) state.
__device__ int g_counts[NUM_CLASSES];
__device__ int g_hits[NUM_CLASSES];

// ---------------------------------------------------------------------------
// Kernel 1: one warp per row. Dual argmax (pred & true), first-index
// tie-break, histogram atomics. Pure streaming — no epilogue fences.
// (Unchanged from R7: 7.3 TB/s, 91.6% of HBM spec.)
// ---------------------------------------------------------------------------
__global__ void __launch_bounds__(MAIN_BLOCK)
argmax_hist_kernel(const float4* __restrict__ y_pred,
                   const float4* __restrict__ y_true) {
    const int warp_id = (blockIdx.x * WARPS_PER_BLOCK) + (threadIdx.x >> 5);
    const int lane    = threadIdx.x & 31;

    const float4* __restrict__ rp = y_pred + (size_t)warp_id * C4;
    const float4* __restrict__ rt = y_true + (size_t)warp_id * C4;

    // Unpredicated loads: clamp index to 249. Duplicated chunk-249 reads are
    // harmless for argmax (strict '>' keeps the first occurrence; cross-lane
    // ties resolve by smaller index in the warp reduce). 16 independent
    // LDG.128 per lane; __ldcs = evict-first (data touched exactly once).
    float4 a[8], b[8];
    int idx[8];
    #pragma unroll
    for (int k = 0; k < 8; k++) {
        const int i = min(k * 32 + lane, C4 - 1);
        idx[k] = i * 4;
        a[k] = __ldcs(rp + i);
        b[k] = __ldcs(rt + i);
    }

    float pbest = -CUDART_INF_F; int pidx = 0;
    float tbest = -CUDART_INF_F; int tidx = 0;
    #pragma unroll
    for (int k = 0; k < 8; k++) {
        const int base = idx[k];
        if (a[k].x > pbest) { pbest = a[k].x; pidx = base + 0; }
        if (a[k].y > pbest) { pbest = a[k].y; pidx = base + 1; }
        if (a[k].z > pbest) { pbest = a[k].z; pidx = base + 2; }
        if (a[k].w > pbest) { pbest = a[k].w; pidx = base + 3; }
        if (b[k].x > tbest) { tbest = b[k].x; tidx = base + 0; }
        if (b[k].y > tbest) { tbest = b[k].y; tidx = base + 1; }
        if (b[k].z > tbest) { tbest = b[k].z; tidx = base + 2; }
        if (b[k].w > tbest) { tbest = b[k].w; tidx = base + 3; }
    }

    // Warp argmax reduce; tie-break toward smaller index (first occurrence).
    #pragma unroll
    for (int off = 16; off > 0; off >>= 1) {
        float pv = __shfl_down_sync(0xFFFFFFFFu, pbest, off);
        int   pi = __shfl_down_sync(0xFFFFFFFFu, pidx,  off);
        if (pv > pbest || (pv == pbest && pi < pidx)) { pbest = pv; pidx = pi; }
        float tv = __shfl_down_sync(0xFFFFFFFFu, tbest, off);
        int   ti = __shfl_down_sync(0xFFFFFFFFu, tidx,  off);
        if (tv > tbest || (tv == tbest && ti < tidx)) { tbest = tv; tidx = ti; }
    }

    if (lane == 0) {
        atomicAdd(&g_counts[tidx], 1);
        if (pidx == tidx) atomicAdd(&g_hits[tidx], 1);
    }
}

// ---------------------------------------------------------------------------
// Kernel 2: 1024 threads, one class per thread, no loops, fast division.
// Reduce 1000 classes -> -mean_recall, then reset histograms for the next
// graph replay.
// ---------------------------------------------------------------------------
__global__ void __launch_bounds__(1024)
finalize_kernel(float* __restrict__ out) {
    const int tid = threadIdx.x;

    float rec = 0.0f, prs = 0.0f;
    int cnt = 0;
    if (tid < NUM_CLASSES) {
        cnt = g_counts[tid];
        if (cnt > 0) {
            prs = 1.0f;
            // MUFU rcp + mul; rel-err ~2^-22, far below the 1e-3 tolerance.
            rec = __fdividef((float)g_hits[tid], (float)cnt);
        }
    }

    // 32-warp reduction: warp shuffle, then one warp over smem.
    __shared__ float s_rec[32];
    __shared__ float s_prs[32];
    #pragma unroll
    for (int off = 16; off > 0; off >>= 1) {
        rec += __shfl_down_sync(0xFFFFFFFFu, rec, off);
        prs += __shfl_down_sync(0xFFFFFFFFu, prs, off);
    }
    const int warp = tid >> 5;
    const int lane = tid & 31;
    if (lane == 0) { s_rec[warp] = rec; s_prs[warp] = prs; }
    __syncthreads();
    if (warp == 0) {
        rec = s_rec[lane];
        prs = s_prs[lane];
        #pragma unroll
        for (int off = 16; off > 0; off >>= 1) {
            rec += __shfl_down_sync(0xFFFFFFFFu, rec, off);
            prs += __shfl_down_sync(0xFFFFFFFFu, prs, off);
        }
        if (lane == 0)
            out[0] = (prs > 0.0f) ? -__fdividef(rec, prs) : 0.0f;
    }

    // Reset for the next replay (reads above are ordered before these writes
    // by the __syncthreads in the reduction path).
    if (tid < NUM_CLASSES) {
        g_counts[tid] = 0;
        g_hits[tid]   = 0;
    }
}

// ---------------------------------------------------------------------------
extern "C" void kernel_launch(void* const* d_in, const int* in_sizes, int n_in,
                              void* d_out, int out_size) {
    const float4* y_pred = (const float4*)d_in[0];
    const float4* y_true = (const float4*)d_in[1];
    float* out = (float*)d_out;

    argmax_hist_kernel<<<GRID_BLOCKS, MAIN_BLOCK>>>(y_pred, y_true);
    finalize_kernel<<<1, 1024>>>(out);
}

// round 10
// speedup vs baseline: 1.0303x; 1.0038x over previous
#include <cuda_runtime.h>
#include <math_constants.h>

#define BATCH 131072
#define NUM_CLASSES 1000
#define C4 250                 // float4 chunks per row (1000 floats)
#define MAIN_BLOCK 256
#define WARPS_PER_BLOCK (MAIN_BLOCK / 32)
#define GRID_BLOCKS (BATCH / WARPS_PER_BLOCK)   // 16384, exact

// Zero-initialized at module load. The finalize kernel re-zeros after use, so
// every graph replay starts from the same (zeroed) state.
__device__ int g_counts[NUM_CLASSES];
__device__ int g_hits[NUM_CLASSES];

// ---------------------------------------------------------------------------
// Kernel 1: one warp per row. Dual argmax (pred & true), first-index
// tie-break, histogram atomics. Pure streaming — no epilogue fences.
// (Unchanged since R7: 7.3 TB/s, 91.6% of HBM spec.)
// ---------------------------------------------------------------------------
__global__ void __launch_bounds__(MAIN_BLOCK)
argmax_hist_kernel(const float4* __restrict__ y_pred,
                   const float4* __restrict__ y_true) {
    const int warp_id = (blockIdx.x * WARPS_PER_BLOCK) + (threadIdx.x >> 5);
    const int lane    = threadIdx.x & 31;

    const float4* __restrict__ rp = y_pred + (size_t)warp_id * C4;
    const float4* __restrict__ rt = y_true + (size_t)warp_id * C4;

    // Unpredicated loads: clamp index to 249. Duplicated chunk-249 reads are
    // harmless for argmax (strict '>' keeps the first occurrence; cross-lane
    // ties resolve by smaller index in the warp reduce). 16 independent
    // LDG.128 per lane; __ldcs = evict-first (data touched exactly once).
    float4 a[8], b[8];
    int idx[8];
    #pragma unroll
    for (int k = 0; k < 8; k++) {
        const int i = min(k * 32 + lane, C4 - 1);
        idx[k] = i * 4;
        a[k] = __ldcs(rp + i);
        b[k] = __ldcs(rt + i);
    }

    float pbest = -CUDART_INF_F; int pidx = 0;
    float tbest = -CUDART_INF_F; int tidx = 0;
    #pragma unroll
    for (int k = 0; k < 8; k++) {
        const int base = idx[k];
        if (a[k].x > pbest) { pbest = a[k].x; pidx = base + 0; }
        if (a[k].y > pbest) { pbest = a[k].y; pidx = base + 1; }
        if (a[k].z > pbest) { pbest = a[k].z; pidx = base + 2; }
        if (a[k].w > pbest) { pbest = a[k].w; pidx = base + 3; }
        if (b[k].x > tbest) { tbest = b[k].x; tidx = base + 0; }
        if (b[k].y > tbest) { tbest = b[k].y; tidx = base + 1; }
        if (b[k].z > tbest) { tbest = b[k].z; tidx = base + 2; }
        if (b[k].w > tbest) { tbest = b[k].w; tidx = base + 3; }
    }

    // Warp argmax reduce; tie-break toward smaller index (first occurrence).
    #pragma unroll
    for (int off = 16; off > 0; off >>= 1) {
        float pv = __shfl_down_sync(0xFFFFFFFFu, pbest, off);
        int   pi = __shfl_down_sync(0xFFFFFFFFu, pidx,  off);
        if (pv > pbest || (pv == pbest && pi < pidx)) { pbest = pv; pidx = pi; }
        float tv = __shfl_down_sync(0xFFFFFFFFu, tbest, off);
        int   ti = __shfl_down_sync(0xFFFFFFFFu, tidx,  off);
        if (tv > tbest || (tv == tbest && ti < tidx)) { tbest = tv; tidx = ti; }
    }

    if (lane == 0) {
        atomicAdd(&g_counts[tidx], 1);
        if (pidx == tidx) atomicAdd(&g_hits[tidx], 1);
    }
}

// ---------------------------------------------------------------------------
// Kernel 2 (PDL secondary): launches concurrently with the primary via
// programmatic stream serialization; its launch ramp overlaps the primary's
// tail. cudaGridDependencySynchronize() gates the histogram reads on the
// primary grid's completion (and makes its memory ops visible).
// ---------------------------------------------------------------------------
__global__ void __launch_bounds__(1024)
finalize_kernel(float* __restrict__ out) {
    cudaGridDependencySynchronize();

    const int tid = threadIdx.x;

    float rec = 0.0f, prs = 0.0f;
    if (tid < NUM_CLASSES) {
        const int cnt = g_counts[tid];
        if (cnt > 0) {
            prs = 1.0f;
            // MUFU rcp + mul; rel-err ~2^-22, far below the 1e-3 tolerance.
            rec = __fdividef((float)g_hits[tid], (float)cnt);
        }
    }

    // 32-warp reduction: warp shuffle, then one warp over smem.
    __shared__ float s_rec[32];
    __shared__ float s_prs[32];
    #pragma unroll
    for (int off = 16; off > 0; off >>= 1) {
        rec += __shfl_down_sync(0xFFFFFFFFu, rec, off);
        prs += __shfl_down_sync(0xFFFFFFFFu, prs, off);
    }
    const int warp = tid >> 5;
    const int lane = tid & 31;
    if (lane == 0) { s_rec[warp] = rec; s_prs[warp] = prs; }
    __syncthreads();
    if (warp == 0) {
        rec = s_rec[lane];
        prs = s_prs[lane];
        #pragma unroll
        for (int off = 16; off > 0; off >>= 1) {
            rec += __shfl_down_sync(0xFFFFFFFFu, rec, off);
            prs += __shfl_down_sync(0xFFFFFFFFu, prs, off);
        }
        if (lane == 0)
            out[0] = (prs > 0.0f) ? -__fdividef(rec, prs) : 0.0f;
    }

    // Reset for the next replay (reads above are ordered before these writes
    // by the __syncthreads in the reduction path).
    if (tid < NUM_CLASSES) {
        g_counts[tid] = 0;
        g_hits[tid]   = 0;
    }
}

// ---------------------------------------------------------------------------
extern "C" void kernel_launch(void* const* d_in, const int* in_sizes, int n_in,
                              void* d_out, int out_size) {
    const float4* y_pred = (const float4*)d_in[0];
    const float4* y_true = (const float4*)d_in[1];
    float* out = (float*)d_out;

    argmax_hist_kernel<<<GRID_BLOCKS, MAIN_BLOCK>>>(y_pred, y_true);

    // PDL launch of the finalize kernel: overlap its launch ramp with the
    // primary kernel's execution.
    cudaLaunchConfig_t cfg = {};
    cfg.gridDim  = dim3(1, 1, 1);
    cfg.blockDim = dim3(1024, 1, 1);
    cfg.dynamicSmemBytes = 0;
    cudaLaunchAttribute attrs[1];
    attrs[0].id = cudaLaunchAttributeProgrammaticStreamSerialization;
    attrs[0].val.programmaticStreamSerializationAllowed = 1;
    cfg.attrs = attrs;
    cfg.numAttrs = 1;
    cudaLaunchKernelEx(&cfg, finalize_kernel, out);
}